// round 9
// baseline (speedup 1.0000x reference)
#include <cuda_runtime.h>
#include <cuda_fp16.h>
#include <mma.h>
#include <cstdint>
#include <cstddef>

using namespace nvcuda;

// ---------------- problem constants ----------------
#define NHEADS   32
#define NTOK     49
#define CDIM     1024
#define HD       32
#define NWIN     64
#define NBATCH   1024
#define MTOT     (NBATCH*NTOK)          // 50176
#define QK_SCALE 0.17677669529663687f   // 32^-0.5

// ---------------- scratch (__device__ globals; no allocs allowed) ----------------
__device__ __half g_xh  [(size_t)MTOT*CDIM];        // x in fp16
__device__ __half g_wqkv[(size_t)3*CDIM*CDIM];      // qkv_w [o][c] fp16
__device__ __half g_wout[(size_t)CDIM*CDIM];        // out_w transposed -> [o][c] fp16
__device__ __half g_q   [(size_t)NBATCH*NHEADS*NTOK*HD];   // [bh][tok][d], pre-scaled
__device__ __half g_k   [(size_t)NBATCH*NHEADS*NTOK*HD];   // [bh][tok][d]
__device__ __half g_v   [(size_t)NBATCH*NHEADS*NTOK*HD];   // [bh][tok][d]
__device__ __half g_ao  [(size_t)MTOT*CDIM];        // attention output [m][h*32+d]
__device__ float  g_bias[NHEADS*NTOK*NTOK];         // gathered rel-pos bias [h][r][c]

// ---------------- converts ----------------
__global__ void cvt_x_k(const float* __restrict__ x) {
    size_t i = (size_t)blockIdx.x * blockDim.x + threadIdx.x;
    size_t n2 = (size_t)MTOT * CDIM / 2;
    if (i < n2) {
        float2 f = ((const float2*)x)[i];
        ((__half2*)g_xh)[i] = make_half2(__float2half_rn(f.x), __float2half_rn(f.y));
    }
}
__global__ void cvt_wqkv_k(const float* __restrict__ w) {
    size_t i = (size_t)blockIdx.x * blockDim.x + threadIdx.x;
    size_t n2 = (size_t)3 * CDIM * CDIM / 2;
    if (i < n2) {
        float2 f = ((const float2*)w)[i];
        ((__half2*)g_wqkv)[i] = make_half2(__float2half_rn(f.x), __float2half_rn(f.y));
    }
}
__global__ void cvt_wout_k(const float* __restrict__ w) {
    int i = blockIdx.x * blockDim.x + threadIdx.x;
    if (i < CDIM * CDIM) {
        int o = i >> 10, c = i & 1023;
        g_wout[i] = __float2half_rn(w[(c << 10) + o]);  // transpose [c][o] -> [o][c]
    }
}
__global__ void build_bias_k(const float* __restrict__ table, const int* __restrict__ rpi) {
    int i = blockIdx.x * blockDim.x + threadIdx.x;
    if (i < NHEADS * NTOK * NTOK) {
        int h = i / (NTOK * NTOK);
        int rc = i % (NTOK * NTOK);
        g_bias[i] = table[rpi[rc] * NHEADS + h];
    }
}

// ---------------- cp.async helpers ----------------
__device__ __forceinline__ void cp16(void* s, const void* g) {
    uint32_t sa = (uint32_t)__cvta_generic_to_shared(s);
    asm volatile("cp.async.cg.shared.global [%0], [%1], 16;" :: "r"(sa), "l"(g) : "memory");
}
__device__ __forceinline__ void cp_commit() {
    asm volatile("cp.async.commit_group;" ::: "memory");
}
template <int N> __device__ __forceinline__ void cp_wait() {
    asm volatile("cp.async.wait_group %0;" :: "n"(N) : "memory");
}

// ---------------- GEMM: C[M,N] = A[M,K] * B[N,K]^T (+bias, fused epilogues) ----------------
// 256x128 CTA tile, 512 threads / 16 warps (8m x 2n), 32x64 warp tiles, BK=32,
// 4-stage cp.async pipeline (122.9 KB smem, 1 CTA/SM, 16 warps for latency hiding).
// EPI 0: QKV gemm  (A=g_xh, B=g_wqkv, N=3072)  -> scatter to g_q (scaled), g_k, g_v
// EPI 1: out proj  (A=g_ao, B=g_wout, N=1024)  -> fp32 d_out
constexpr int BM = 256, BN = 128, BK = 32, STAGES = 4, GTHREADS = 512;
constexpr int ASTR = 40;                       // smem row stride (halves)
constexpr int SMEM_A_H = STAGES * BM * ASTR;   // halves
constexpr int SMEM_B_H = STAGES * BN * ASTR;
constexpr int GEMM_SMEM_BYTES = (SMEM_A_H + SMEM_B_H) * 2;   // 122880 B

template <int EPI>
__global__ void __launch_bounds__(GTHREADS, 1)
gemm_tn(const float* __restrict__ bias, float* __restrict__ outF) {
    constexpr int K = 1024;
    const __half* __restrict__ A  = (EPI == 0) ? g_xh : g_ao;
    const __half* __restrict__ Bw = (EPI == 0) ? g_wqkv : g_wout;

    extern __shared__ __align__(16) char smraw[];
    __half* As = (__half*)smraw;
    __half* Bs = As + SMEM_A_H;
    float*  Cs = (float*)smraw;   // epilogue alias: 128 x 132 fp32 = 67584 B

    const int tid = threadIdx.x;
    const int wid = tid >> 5;
    const int wm = wid >> 1, wn = wid & 1;     // 8x2 warp grid, 32x64 warp tiles
    const int n0 = blockIdx.x * BN;
    const int m0 = blockIdx.y * BM;

    wmma::fragment<wmma::accumulator, 16, 16, 16, float> cf[2][4];
#pragma unroll
    for (int i = 0; i < 2; i++)
#pragma unroll
        for (int j = 0; j < 4; j++) wmma::fill_fragment(cf[i][j], 0.0f);

    auto load_stage = [&](int s, int kt) {
        const __half* gA = A + (size_t)m0 * K + kt * BK;
        // A tile: 256 rows x 32 cols -> 1024 x cp16; 512 threads x 2
#pragma unroll
        for (int i = 0; i < 2; i++) {
            int cc = tid + i * GTHREADS;           // 0..1023
            int r = cc >> 2, col = (cc & 3) * 8;
            cp16(As + s * BM * ASTR + r * ASTR + col, gA + (size_t)r * K + col);
        }
        // B tile: 128 rows x 32 cols -> 512 x cp16; one per thread
        {
            int r = tid >> 2, col = (tid & 3) * 8;
            cp16(Bs + s * BN * ASTR + r * ASTR + col,
                 Bw + (size_t)(n0 + r) * K + kt * BK + col);
        }
    };

    constexpr int KT = K / BK;   // 32
#pragma unroll
    for (int s = 0; s < STAGES - 1; s++) { load_stage(s, s); cp_commit(); }

    for (int kt = 0; kt < KT; ++kt) {
        cp_wait<STAGES - 2>();
        __syncthreads();
        int buf = kt % STAGES;
        if (kt + STAGES - 1 < KT) load_stage((kt + STAGES - 1) % STAGES, kt + STAGES - 1);
        cp_commit();
        const __half* Ab = As + buf * BM * ASTR;
        const __half* Bb = Bs + buf * BN * ASTR;
#pragma unroll
        for (int kk = 0; kk < 2; ++kk) {
            wmma::fragment<wmma::matrix_a, 16, 16, 16, __half, wmma::row_major> af[2];
#pragma unroll
            for (int i = 0; i < 2; i++)
                wmma::load_matrix_sync(af[i], Ab + (wm * 32 + i * 16) * ASTR + kk * 16, ASTR);
#pragma unroll
            for (int j = 0; j < 4; j++) {
                wmma::fragment<wmma::matrix_b, 16, 16, 16, __half, wmma::col_major> bf;
                wmma::load_matrix_sync(bf, Bb + (wn * 64 + j * 16) * ASTR + kk * 16, ASTR);
                wmma::mma_sync(cf[0][j], af[0], bf, cf[0][j]);
                wmma::mma_sync(cf[1][j], af[1], bf, cf[1][j]);
            }
        }
    }
    cp_wait<0>();

    // ---- epilogue: two 128-row halves through smem ----
#pragma unroll
    for (int half = 0; half < 2; half++) {
        __syncthreads();
        if ((wm >> 2) == half) {
            int rw = (wm & 3) * 32;
#pragma unroll
            for (int i = 0; i < 2; i++)
#pragma unroll
                for (int j = 0; j < 4; j++)
                    wmma::store_matrix_sync(Cs + (rw + i * 16) * 132 + wn * 64 + j * 16,
                                            cf[i][j], 132, wmma::mem_row_major);
        }
        __syncthreads();
        if (EPI == 0) {
            for (int idx = tid; idx < 128 * 64; idx += GTHREADS) {
                int r = idx >> 6, cc = (idx & 63) * 2;
                float2 v = *(const float2*)&Cs[r * 132 + cc];
                int m = m0 + half * 128 + r;
                int b = m / NTOK, tok = m - b * NTOK;
                int o = n0 + cc;
                int sel = o >> 10;                 // 0=q 1=k 2=v
                int h = (o >> 5) & 31, d = o & 31;
                float sc = (sel == 0) ? QK_SCALE : 1.0f;
                float v0 = (v.x + bias[o])     * sc;
                float v1 = (v.y + bias[o + 1]) * sc;
                __half* dst = (sel == 0 ? g_q : (sel == 1 ? g_k : g_v))
                              + ((size_t)(b * NHEADS + h) * NTOK + tok) * HD + d;
                *(__half2*)dst = __floats2half2_rn(v0, v1);
            }
        } else {
            for (int idx = tid; idx < 128 * 32; idx += GTHREADS) {
                int r = idx >> 5, c4 = (idx & 31) * 4;
                float4 v = *(const float4*)&Cs[r * 132 + c4];
                int m = m0 + half * 128 + r;
                v.x += bias[n0 + c4];
                v.y += bias[n0 + c4 + 1];
                v.z += bias[n0 + c4 + 2];
                v.w += bias[n0 + c4 + 3];
                *(float4*)(outF + (size_t)m * CDIM + n0 + c4) = v;
            }
        }
    }
}

// ---------------- attention: one CTA per (b, head) ----------------
__global__ void __launch_bounds__(128) attn_kernel(const float* __restrict__ mask) {
    const int bh = blockIdx.x;
    const int b = bh >> 5;
    const int h = bh & 31;
    const int w = b & (NWIN - 1);
    const int tid = threadIdx.x;
    const int wid = tid >> 5;

    __shared__ __align__(16) __half qs[64][40];
    __shared__ __align__(16) __half ks[64][40];
    __shared__ __align__(16) __half vs[32][72];
    __shared__ __align__(16) __half P[64][72];
    __shared__ __align__(16) float  S[64][68];   // scores, then reused for O
    __shared__ float rinv[64];

    // zero pad regions
    for (int i = tid; i < 64 * 40; i += 128) { ((__half*)qs)[i] = __float2half_rn(0.f); ((__half*)ks)[i] = __float2half_rn(0.f); }
    for (int i = tid; i < 32 * 72; i += 128) ((__half*)vs)[i] = __float2half_rn(0.f);
    __syncthreads();

    const __half* gq = g_q + (size_t)bh * NTOK * HD;
    const __half* gk = g_k + (size_t)bh * NTOK * HD;
    for (int i = tid; i < 784; i += 128) {
        int t = i >> 4, p = i & 15;
        *(uint32_t*)&qs[t][p * 2] = ((const uint32_t*)gq)[i];
        *(uint32_t*)&ks[t][p * 2] = ((const uint32_t*)gk)[i];
    }
    // V stored [tok][d]; transpose into vs[d][t]
    const __half* gv = g_v + (size_t)bh * NTOK * HD;
    for (int i = tid; i < NTOK * HD; i += 128) {
        int t = i >> 5, d = i & 31;
        vs[d][t] = gv[i];
    }
    __syncthreads();

    // S = (Q*scale) K^T   (scale pre-folded into Q)
    {
        wmma::fragment<wmma::accumulator, 16, 16, 16, float> c[4];
#pragma unroll
        for (int j = 0; j < 4; j++) wmma::fill_fragment(c[j], 0.0f);
#pragma unroll
        for (int kk = 0; kk < 2; kk++) {
            wmma::fragment<wmma::matrix_a, 16, 16, 16, __half, wmma::row_major> a;
            wmma::load_matrix_sync(a, &qs[wid * 16][kk * 16], 40);
#pragma unroll
            for (int j = 0; j < 4; j++) {
                wmma::fragment<wmma::matrix_b, 16, 16, 16, __half, wmma::col_major> bf;
                wmma::load_matrix_sync(bf, &ks[j * 16][kk * 16], 40);
                wmma::mma_sync(c[j], a, bf, c[j]);
            }
        }
#pragma unroll
        for (int j = 0; j < 4; j++)
            wmma::store_matrix_sync(&S[wid * 16][j * 16], c[j], 68, wmma::mem_row_major);
    }
    __syncthreads();

    // bias + mask + softmax (unnormalized exp; 1/rowsum folded into epilogue)
    if (tid < 64) {
        int r = tid;
        if (r < 49) {
            const float* bp = g_bias + (h * NTOK + r) * NTOK;
            const float* mp = mask + ((size_t)w * NTOK + r) * NTOK;
            float mx = -1e30f;
            for (int c = 0; c < 49; c++) {
                float s = S[r][c] + bp[c] + mp[c];
                S[r][c] = s;
                mx = fmaxf(mx, s);
            }
            float sum = 0.f;
            for (int c = 0; c < 49; c++) {
                float e = __expf(S[r][c] - mx);
                sum += e;
                P[r][c] = __float2half_rn(e);
            }
            for (int c = 49; c < 64; c++) P[r][c] = __float2half_rn(0.f);
            rinv[r] = 1.0f / sum;
        } else {
            for (int c = 0; c < 64; c++) P[r][c] = __float2half_rn(0.f);
            rinv[r] = 0.f;
        }
    }
    __syncthreads();

    // O = P V
    {
        wmma::fragment<wmma::accumulator, 16, 16, 16, float> c2[2];
#pragma unroll
        for (int j = 0; j < 2; j++) wmma::fill_fragment(c2[j], 0.0f);
#pragma unroll
        for (int kk = 0; kk < 4; kk++) {
            wmma::fragment<wmma::matrix_a, 16, 16, 16, __half, wmma::row_major> a;
            wmma::load_matrix_sync(a, &P[wid * 16][kk * 16], 72);
#pragma unroll
            for (int j = 0; j < 2; j++) {
                wmma::fragment<wmma::matrix_b, 16, 16, 16, __half, wmma::col_major> bf;
                wmma::load_matrix_sync(bf, &vs[j * 16][kk * 16], 72);
                wmma::mma_sync(c2[j], a, bf, c2[j]);
            }
        }
        __syncthreads();
#pragma unroll
        for (int j = 0; j < 2; j++)
            wmma::store_matrix_sync(&S[wid * 16][j * 16], c2[j], 68, wmma::mem_row_major);
    }
    __syncthreads();

    __half* out = g_ao + ((size_t)b * NTOK) * CDIM + h * HD;
    for (int i = tid; i < NTOK * HD; i += 128) {
        int t = i >> 5, d = i & 31;
        out[(size_t)t * CDIM + d] = __float2half_rn(S[t][d] * rinv[t]);
    }
}

// ---------------- launch ----------------
extern "C" void kernel_launch(void* const* d_in, const int* in_sizes, int n_in,
                              void* d_out, int out_size) {
    const float* x    = (const float*)d_in[0];
    const float* mask = (const float*)d_in[1];
    int off = (in_sizes[2] < 16) ? 3 : 2;   // hedge for scalar "nw" input
    const float* qkv_w = (const float*)d_in[off + 0];
    const float* qkv_b = (const float*)d_in[off + 1];
    const float* table = (const float*)d_in[off + 2];
    const float* out_w = (const float*)d_in[off + 3];
    const float* out_b = (const float*)d_in[off + 4];
    const int*   rpi   = (const int*)  d_in[off + 5];
    float* out = (float*)d_out;

    cudaFuncSetAttribute(gemm_tn<0>, cudaFuncAttributeMaxDynamicSharedMemorySize, GEMM_SMEM_BYTES);
    cudaFuncSetAttribute(gemm_tn<1>, cudaFuncAttributeMaxDynamicSharedMemorySize, GEMM_SMEM_BYTES);

    {
        long n2 = (long)MTOT * CDIM / 2;
        cvt_x_k<<<(unsigned)((n2 + 255) / 256), 256>>>(x);
    }
    {
        long n2 = (long)3 * CDIM * CDIM / 2;
        cvt_wqkv_k<<<(unsigned)((n2 + 255) / 256), 256>>>(qkv_w);
    }
    cvt_wout_k<<<(CDIM * CDIM + 255) / 256, 256>>>(out_w);
    build_bias_k<<<(NHEADS * NTOK * NTOK + 255) / 256, 256>>>(table, rpi);

    gemm_tn<0><<<dim3(3 * CDIM / BN, MTOT / BM), GTHREADS, GEMM_SMEM_BYTES>>>(qkv_b, nullptr);
    attn_kernel<<<NBATCH * NHEADS, 128>>>(mask);
    gemm_tn<1><<<dim3(CDIM / BN, MTOT / BM), GTHREADS, GEMM_SMEM_BYTES>>>(out_b, out);
}

// round 14
// speedup vs baseline: 1.0484x; 1.0484x over previous
#include <cuda_runtime.h>
#include <cuda_fp16.h>
#include <mma.h>
#include <cstdint>
#include <cstddef>

using namespace nvcuda;

// ---------------- problem constants ----------------
#define NHEADS   32
#define NTOK     49
#define CDIM     1024
#define HD       32
#define NWIN     64
#define NBATCH   1024
#define MTOT     (NBATCH*NTOK)          // 50176
#define QK_SCALE 0.17677669529663687f   // 32^-0.5

// ---------------- scratch (__device__ globals; no allocs allowed) ----------------
__device__ __half g_xh  [(size_t)MTOT*CDIM];        // x in fp16
__device__ __half g_wqkv[(size_t)3*CDIM*CDIM];      // qkv_w [o][c] fp16
__device__ __half g_wout[(size_t)CDIM*CDIM];        // out_w transposed -> [o][c] fp16
__device__ __half g_q   [(size_t)NBATCH*NHEADS*NTOK*HD];   // [bh][tok][d], pre-scaled
__device__ __half g_k   [(size_t)NBATCH*NHEADS*NTOK*HD];   // [bh][tok][d]
__device__ __half g_v   [(size_t)NBATCH*NHEADS*NTOK*HD];   // [bh][tok][d]
__device__ __half g_ao  [(size_t)MTOT*CDIM];        // attention output [m][h*32+d]
__device__ float  g_bias[NHEADS*NTOK*NTOK];         // gathered rel-pos bias [h][r][c]

// ---------------- converts ----------------
__global__ void cvt_x_k(const float* __restrict__ x) {
    size_t i = (size_t)blockIdx.x * blockDim.x + threadIdx.x;
    size_t n2 = (size_t)MTOT * CDIM / 2;
    if (i < n2) {
        float2 f = ((const float2*)x)[i];
        ((__half2*)g_xh)[i] = make_half2(__float2half_rn(f.x), __float2half_rn(f.y));
    }
}
__global__ void cvt_wqkv_k(const float* __restrict__ w) {
    size_t i = (size_t)blockIdx.x * blockDim.x + threadIdx.x;
    size_t n2 = (size_t)3 * CDIM * CDIM / 2;
    if (i < n2) {
        float2 f = ((const float2*)w)[i];
        ((__half2*)g_wqkv)[i] = make_half2(__float2half_rn(f.x), __float2half_rn(f.y));
    }
}
__global__ void cvt_wout_k(const float* __restrict__ w) {
    int i = blockIdx.x * blockDim.x + threadIdx.x;
    if (i < CDIM * CDIM) {
        int o = i >> 10, c = i & 1023;
        g_wout[i] = __float2half_rn(w[(c << 10) + o]);  // transpose [c][o] -> [o][c]
    }
}
__global__ void build_bias_k(const float* __restrict__ table, const int* __restrict__ rpi) {
    int i = blockIdx.x * blockDim.x + threadIdx.x;
    if (i < NHEADS * NTOK * NTOK) {
        int h = i / (NTOK * NTOK);
        int rc = i % (NTOK * NTOK);
        g_bias[i] = table[rpi[rc] * NHEADS + h];
    }
}

// ---------------- cp.async helpers ----------------
__device__ __forceinline__ void cp16(void* s, const void* g) {
    uint32_t sa = (uint32_t)__cvta_generic_to_shared(s);
    asm volatile("cp.async.cg.shared.global [%0], [%1], 16;" :: "r"(sa), "l"(g) : "memory");
}
__device__ __forceinline__ void cp_commit() {
    asm volatile("cp.async.commit_group;" ::: "memory");
}
template <int N> __device__ __forceinline__ void cp_wait() {
    asm volatile("cp.async.wait_group %0;" :: "n"(N) : "memory");
}

// ---------------- GEMM: C[M,N] = A[M,K] * B[N,K]^T (+bias, fused epilogues) ----------------
// 256x128 CTA tile, 8 warps (4m x 2n) with 64x64 warp tiles, BK=32, 3-stage cp.async.
// (Best measured config: R6, 2319 us.)
constexpr int BM = 256, BN = 128, BK = 32, STAGES = 3, GTHREADS = 256;
constexpr int ASTR = 40;                       // smem row stride (halves)
constexpr int SMEM_A_H = STAGES * BM * ASTR;   // halves
constexpr int SMEM_B_H = STAGES * BN * ASTR;
constexpr int GEMM_SMEM_BYTES = (SMEM_A_H + SMEM_B_H) * 2;   // 92160 B

template <int EPI>
__global__ void __launch_bounds__(GTHREADS, 1)
gemm_tn(const float* __restrict__ bias, float* __restrict__ outF) {
    constexpr int K = 1024;
    const __half* __restrict__ A  = (EPI == 0) ? g_xh : g_ao;
    const __half* __restrict__ Bw = (EPI == 0) ? g_wqkv : g_wout;

    extern __shared__ __align__(16) char smraw[];
    __half* As = (__half*)smraw;
    __half* Bs = As + SMEM_A_H;
    float*  Cs = (float*)smraw;   // epilogue alias: 128 x 132 fp32 = 67584 B

    const int tid = threadIdx.x;
    const int wid = tid >> 5;
    const int wm = wid >> 1, wn = wid & 1;     // 4x2 warp grid, 64x64 warp tiles
    const int n0 = blockIdx.x * BN;
    const int m0 = blockIdx.y * BM;

    wmma::fragment<wmma::accumulator, 16, 16, 16, float> cf[4][4];
#pragma unroll
    for (int i = 0; i < 4; i++)
#pragma unroll
        for (int j = 0; j < 4; j++) wmma::fill_fragment(cf[i][j], 0.0f);

    auto load_stage = [&](int s, int kt) {
        const __half* gA = A + (size_t)m0 * K + kt * BK;
#pragma unroll
        for (int i = 0; i < 4; i++) {
            int cc = tid + i * GTHREADS;           // 0..1023
            int r = cc >> 2, col = (cc & 3) * 8;
            cp16(As + s * BM * ASTR + r * ASTR + col, gA + (size_t)r * K + col);
        }
#pragma unroll
        for (int i = 0; i < 2; i++) {
            int cc = tid + i * GTHREADS;           // 0..511
            int r = cc >> 2, col = (cc & 3) * 8;
            cp16(Bs + s * BN * ASTR + r * ASTR + col,
                 Bw + (size_t)(n0 + r) * K + kt * BK + col);
        }
    };

    constexpr int KT = K / BK;   // 32
#pragma unroll
    for (int s = 0; s < STAGES - 1; s++) { load_stage(s, s); cp_commit(); }

    for (int kt = 0; kt < KT; ++kt) {
        cp_wait<STAGES - 2>();
        __syncthreads();
        int buf = kt % STAGES;
        if (kt + STAGES - 1 < KT) load_stage((kt + STAGES - 1) % STAGES, kt + STAGES - 1);
        cp_commit();
        const __half* Ab = As + buf * BM * ASTR;
        const __half* Bb = Bs + buf * BN * ASTR;
#pragma unroll
        for (int kk = 0; kk < 2; ++kk) {
            wmma::fragment<wmma::matrix_a, 16, 16, 16, __half, wmma::row_major> af[4];
            wmma::fragment<wmma::matrix_b, 16, 16, 16, __half, wmma::col_major> bf[4];
#pragma unroll
            for (int i = 0; i < 4; i++)
                wmma::load_matrix_sync(af[i], Ab + (wm * 64 + i * 16) * ASTR + kk * 16, ASTR);
#pragma unroll
            for (int j = 0; j < 4; j++)
                wmma::load_matrix_sync(bf[j], Bb + (wn * 64 + j * 16) * ASTR + kk * 16, ASTR);
#pragma unroll
            for (int i = 0; i < 4; i++)
#pragma unroll
                for (int j = 0; j < 4; j++)
                    wmma::mma_sync(cf[i][j], af[i], bf[j], cf[i][j]);
        }
    }
    cp_wait<0>();

    // ---- epilogue: two 128-row halves through smem ----
#pragma unroll
    for (int half = 0; half < 2; half++) {
        __syncthreads();
        if ((wm >> 1) == half) {
            int rw = (wm & 1) * 64;
#pragma unroll
            for (int i = 0; i < 4; i++)
#pragma unroll
                for (int j = 0; j < 4; j++)
                    wmma::store_matrix_sync(Cs + (rw + i * 16) * 132 + wn * 64 + j * 16,
                                            cf[i][j], 132, wmma::mem_row_major);
        }
        __syncthreads();
        if (EPI == 0) {
            for (int idx = tid; idx < 128 * 64; idx += GTHREADS) {
                int r = idx >> 6, cc = (idx & 63) * 2;
                float2 v = *(const float2*)&Cs[r * 132 + cc];
                int m = m0 + half * 128 + r;
                int b = m / NTOK, tok = m - b * NTOK;
                int o = n0 + cc;
                int sel = o >> 10;                 // 0=q 1=k 2=v
                int h = (o >> 5) & 31, d = o & 31;
                float sc = (sel == 0) ? QK_SCALE : 1.0f;
                float v0 = (v.x + bias[o])     * sc;
                float v1 = (v.y + bias[o + 1]) * sc;
                __half* dst = (sel == 0 ? g_q : (sel == 1 ? g_k : g_v))
                              + ((size_t)(b * NHEADS + h) * NTOK + tok) * HD + d;
                *(__half2*)dst = __floats2half2_rn(v0, v1);
            }
        } else {
            for (int idx = tid; idx < 128 * 32; idx += GTHREADS) {
                int r = idx >> 5, c4 = (idx & 31) * 4;
                float4 v = *(const float4*)&Cs[r * 132 + c4];
                int m = m0 + half * 128 + r;
                v.x += bias[n0 + c4];
                v.y += bias[n0 + c4 + 1];
                v.z += bias[n0 + c4 + 2];
                v.w += bias[n0 + c4 + 3];
                *(float4*)(outF + (size_t)m * CDIM + n0 + c4) = v;
            }
        }
    }
}

// ---------------- attention: one CTA per (b, head) ----------------
__global__ void __launch_bounds__(128) attn_kernel(const float* __restrict__ mask) {
    const int bh = blockIdx.x;
    const int b = bh >> 5;
    const int h = bh & 31;
    const int w = b & (NWIN - 1);
    const int tid = threadIdx.x;
    const int wid = tid >> 5;

    __shared__ __align__(16) __half qs[64][40];
    __shared__ __align__(16) __half ks[64][40];
    __shared__ __align__(16) __half vs[32][72];
    __shared__ __align__(16) __half P[64][72];
    __shared__ __align__(16) float  S[64][68];   // scores, then reused for O
    __shared__ float rinv[64];

    // zero pad regions
    for (int i = tid; i < 64 * 40; i += 128) { ((__half*)qs)[i] = __float2half_rn(0.f); ((__half*)ks)[i] = __float2half_rn(0.f); }
    for (int i = tid; i < 32 * 72; i += 128) ((__half*)vs)[i] = __float2half_rn(0.f);
    __syncthreads();

    const __half* gq = g_q + (size_t)bh * NTOK * HD;
    const __half* gk = g_k + (size_t)bh * NTOK * HD;
    for (int i = tid; i < 784; i += 128) {
        int t = i >> 4, p = i & 15;
        *(uint32_t*)&qs[t][p * 2] = ((const uint32_t*)gq)[i];
        *(uint32_t*)&ks[t][p * 2] = ((const uint32_t*)gk)[i];
    }
    // V stored [tok][d]; transpose into vs[d][t]
    const __half* gv = g_v + (size_t)bh * NTOK * HD;
    for (int i = tid; i < NTOK * HD; i += 128) {
        int t = i >> 5, d = i & 31;
        vs[d][t] = gv[i];
    }
    __syncthreads();

    // S = (Q*scale) K^T   (scale pre-folded into Q)
    {
        wmma::fragment<wmma::accumulator, 16, 16, 16, float> c[4];
#pragma unroll
        for (int j = 0; j < 4; j++) wmma::fill_fragment(c[j], 0.0f);
#pragma unroll
        for (int kk = 0; kk < 2; kk++) {
            wmma::fragment<wmma::matrix_a, 16, 16, 16, __half, wmma::row_major> a;
            wmma::load_matrix_sync(a, &qs[wid * 16][kk * 16], 40);
#pragma unroll
            for (int j = 0; j < 4; j++) {
                wmma::fragment<wmma::matrix_b, 16, 16, 16, __half, wmma::col_major> bf;
                wmma::load_matrix_sync(bf, &ks[j * 16][kk * 16], 40);
                wmma::mma_sync(c[j], a, bf, c[j]);
            }
        }
#pragma unroll
        for (int j = 0; j < 4; j++)
            wmma::store_matrix_sync(&S[wid * 16][j * 16], c[j], 68, wmma::mem_row_major);
    }
    __syncthreads();

    // bias + mask + softmax, 2 threads per row.
    // NOTE: shuffles are hoisted out of the divergent branches — every lane of
    // every warp executes both __shfl_xor_sync (inactive rows contribute
    // neutral values), so full-mask sync shuffles are always convergent.
    {
        int r = tid >> 1;          // 0..63
        int hf = tid & 1;          // 0: cols 0..24, 1: cols 25..48
        bool active = (r < 49);
        int c0 = hf ? 25 : 0;
        int c1 = hf ? 49 : 25;
        const float* bp = g_bias + (h * NTOK + r) * NTOK;
        const float* mp = mask + ((size_t)w * NTOK + r) * NTOK;

        float mx = -1e30f;
        if (active) {
            for (int c = c0; c < c1; c++) {
                float s = S[r][c] + bp[c] + mp[c];
                S[r][c] = s;
                mx = fmaxf(mx, s);
            }
        }
        mx = fmaxf(mx, __shfl_xor_sync(0xFFFFFFFFu, mx, 1));

        float sum = 0.f;
        if (active) {
            for (int c = c0; c < c1; c++) {
                float e = __expf(S[r][c] - mx);
                sum += e;
                P[r][c] = __float2half_rn(e);
            }
        }
        sum += __shfl_xor_sync(0xFFFFFFFFu, sum, 1);

        if (active) {
            if (hf) {
                for (int c = 49; c < 64; c++) P[r][c] = __float2half_rn(0.f);
            } else {
                rinv[r] = 1.0f / sum;
            }
        } else {
            // rows 49..63: zero this half of the padded P row
            int z0 = hf ? 32 : 0;
            for (int c = z0; c < z0 + 32; c++) P[r][c] = __float2half_rn(0.f);
            if (!hf) rinv[r] = 0.f;
        }
    }
    __syncthreads();

    // O = P V
    {
        wmma::fragment<wmma::accumulator, 16, 16, 16, float> c2[2];
#pragma unroll
        for (int j = 0; j < 2; j++) wmma::fill_fragment(c2[j], 0.0f);
#pragma unroll
        for (int kk = 0; kk < 4; kk++) {
            wmma::fragment<wmma::matrix_a, 16, 16, 16, __half, wmma::row_major> a;
            wmma::load_matrix_sync(a, &P[wid * 16][kk * 16], 72);
#pragma unroll
            for (int j = 0; j < 2; j++) {
                wmma::fragment<wmma::matrix_b, 16, 16, 16, __half, wmma::col_major> bf;
                wmma::load_matrix_sync(bf, &vs[j * 16][kk * 16], 72);
                wmma::mma_sync(c2[j], a, bf, c2[j]);
            }
        }
        __syncthreads();
#pragma unroll
        for (int j = 0; j < 2; j++)
            wmma::store_matrix_sync(&S[wid * 16][j * 16], c2[j], 68, wmma::mem_row_major);
    }
    __syncthreads();

    __half* out = g_ao + ((size_t)b * NTOK) * CDIM + h * HD;
    for (int i = tid; i < NTOK * HD; i += 128) {
        int t = i >> 5, d = i & 31;
        out[(size_t)t * CDIM + d] = __float2half_rn(S[t][d] * rinv[t]);
    }
}

// ---------------- launch ----------------
extern "C" void kernel_launch(void* const* d_in, const int* in_sizes, int n_in,
                              void* d_out, int out_size) {
    const float* x    = (const float*)d_in[0];
    const float* mask = (const float*)d_in[1];
    int off = (in_sizes[2] < 16) ? 3 : 2;   // hedge for scalar "nw" input
    const float* qkv_w = (const float*)d_in[off + 0];
    const float* qkv_b = (const float*)d_in[off + 1];
    const float* table = (const float*)d_in[off + 2];
    const float* out_w = (const float*)d_in[off + 3];
    const float* out_b = (const float*)d_in[off + 4];
    const int*   rpi   = (const int*)  d_in[off + 5];
    float* out = (float*)d_out;

    cudaFuncSetAttribute(gemm_tn<0>, cudaFuncAttributeMaxDynamicSharedMemorySize, GEMM_SMEM_BYTES);
    cudaFuncSetAttribute(gemm_tn<1>, cudaFuncAttributeMaxDynamicSharedMemorySize, GEMM_SMEM_BYTES);

    // Launch order arranged so the profiled slot lands on the heavy kernels:
    // 1 cvt_x, 2 cvt_wqkv, 3 build_bias, 4 gemm0, 5 cvt_wout, 6 attn, 7 gemm1
    {
        long n2 = (long)MTOT * CDIM / 2;
        cvt_x_k<<<(unsigned)((n2 + 255) / 256), 256>>>(x);
    }
    {
        long n2 = (long)3 * CDIM * CDIM / 2;
        cvt_wqkv_k<<<(unsigned)((n2 + 255) / 256), 256>>>(qkv_w);
    }
    build_bias_k<<<(NHEADS * NTOK * NTOK + 255) / 256, 256>>>(table, rpi);

    gemm_tn<0><<<dim3(3 * CDIM / BN, MTOT / BM), GTHREADS, GEMM_SMEM_BYTES>>>(qkv_b, nullptr);

    cvt_wout_k<<<(CDIM * CDIM + 255) / 256, 256>>>(out_w);

    attn_kernel<<<NBATCH * NHEADS, 128>>>(mask);
    gemm_tn<1><<<dim3(CDIM / BN, MTOT / BM), GTHREADS, GEMM_SMEM_BYTES>>>(out_b, out);
}